// round 8
// baseline (speedup 1.0000x reference)
#include <cuda_runtime.h>
#include <math.h>
#include <stdint.h>

#define N_ROWS 16384
#define D_DIM  2048
#define E_DIM  64
#define BM     64
#define KT     32
#define NT     (D_DIM / KT)        // 64
#define THREADS 256
#define SXS    36                  // x tile row stride (floats), conflict-free
#define X_BYTES (BM * SXS * 4)     // 9216
#define B_BYTES (4 * 64 * 4 * 16)  // 4 k8-chunks x 64 n x 4 q x float4 = 16384
#define STAGE   (X_BYTES + B_BYTES) // 25600
#define SMEM_TOTAL (2 * STAGE + 256)
#define TAU 1e-4f
#define MAXFLAG 64

__device__ __forceinline__ uint32_t smem_u32(const void* p) {
    return (uint32_t)__cvta_generic_to_shared(p);
}
__device__ __forceinline__ void cp_async16(uint32_t dst, const void* src) {
    asm volatile("cp.async.cg.shared.global [%0], [%1], 16;\n" :: "r"(dst), "l"(src));
}
__device__ __forceinline__ uint32_t tf32_bits(float x) {
    uint32_t r;
    asm("cvt.rna.tf32.f32 %0, %1;" : "=r"(r) : "f"(x));
    return r;
}
__device__ __forceinline__ void mma_tf32(float* c, const uint32_t* a,
                                         uint32_t b0, uint32_t b1) {
    asm volatile(
        "mma.sync.aligned.m16n8k8.row.col.f32.tf32.tf32.f32 "
        "{%0,%1,%2,%3}, {%4,%5,%6,%7}, {%8,%9}, {%0,%1,%2,%3};"
        : "+f"(c[0]), "+f"(c[1]), "+f"(c[2]), "+f"(c[3])
        : "r"(a[0]), "r"(a[1]), "r"(a[2]), "r"(a[3]), "r"(b0), "r"(b1));
}

// W packed fragment-ready: [chunk c=k/8][n][q] float4 {hi(k0+q), hi(k0+q+4), lo(k0+q), lo(k0+q+4)}
__device__ float4 g_wb[256 * 64 * 4];
// exact W, K-major: g_wk[e][k]
__device__ float g_wk[E_DIM * D_DIM];

__global__ void wpack_kernel(const float* __restrict__ W) {
    int idx = blockIdx.x * blockDim.x + threadIdx.x;   // 65536
    {
        int q = idx & 3, n = (idx >> 2) & 63, c = idx >> 8;
        int k = c * 8 + q;
        float w0 = W[(size_t)k * E_DIM + n];
        float w1 = W[(size_t)(k + 4) * E_DIM + n];
        uint32_t h0 = tf32_bits(w0), h1 = tf32_bits(w1);
        float4 v;
        v.x = __uint_as_float(h0);
        v.y = __uint_as_float(h1);
        v.z = __uint_as_float(tf32_bits(w0 - __uint_as_float(h0)));
        v.w = __uint_as_float(tf32_bits(w1 - __uint_as_float(h1)));
        g_wb[idx] = v;
    }
    {   // exact copy, coalesced writes
        int e  = idx >> 10;            // 0..63
        int k2 = (idx & 1023) * 2;     // 0..2046
        g_wk[(size_t)e * D_DIM + k2]     = W[(size_t)k2 * E_DIM + e];
        g_wk[(size_t)e * D_DIM + k2 + 1] = W[(size_t)(k2 + 1) * E_DIM + e];
    }
}

__global__ __launch_bounds__(THREADS, 2)
void router_main(const float* __restrict__ x,
                 const float* __restrict__ bias,
                 float* __restrict__ out_mask,
                 float* __restrict__ out_idx,
                 int write_idx)
{
    extern __shared__ char smem[];
    __shared__ int   s_cnt;
    __shared__ int   s_fr[MAXFLAG];
    __shared__ int4  s_fc[MAXFLAG];
    __shared__ float s_fs[MAXFLAG];
    __shared__ float s_fm[MAXFLAG];

    const uint32_t sb = smem_u32(smem);
    const int tid  = threadIdx.x;
    const int wid  = tid >> 5;
    const int lane = tid & 31;
    const int gid  = lane >> 2;      // groupID 0..7
    const int tig  = lane & 3;       // thread-in-group 0..3
    const int rb   = (wid & 3) * 16; // warp row block (M=16)
    const int kh   = wid >> 2;       // K half: chunks {kh*2, kh*2+1} of each tile
    const int row0 = blockIdx.x * BM;

    if (tid < E_DIM) ((float*)(smem + 2 * STAGE))[tid] = bias[tid];
    if (tid == 0) s_cnt = 0;

    float acc[8][4];
#pragma unroll
    for (int j = 0; j < 8; j++)
#pragma unroll
        for (int q = 0; q < 4; q++) acc[j][q] = 0.0f;

    auto issue_loads = [&](int t) {
        const int s = t & 1;
#pragma unroll
        for (int p = 0; p < 2; p++) {               // x: 64 rows x 8 float4
            int id = tid + p * THREADS;
            int r = id >> 3, c = id & 7;
            cp_async16(sb + s * STAGE + r * (SXS * 4) + c * 16,
                       x + (size_t)(row0 + r) * D_DIM + t * KT + c * 4);
        }
#pragma unroll
        for (int p = 0; p < 4; p++) {               // B: contiguous 16KB
            int id = tid + p * THREADS;
            cp_async16(sb + s * STAGE + X_BYTES + id * 16,
                       (const char*)g_wb + (size_t)t * B_BYTES + id * 16);
        }
        asm volatile("cp.async.commit_group;\n");
    };

    auto compute_tile = [&](int s) {
        const float* sx = (const float*)(smem + s * STAGE);
        const char*  sB = smem + s * STAGE + X_BYTES;
#pragma unroll
        for (int kk = 0; kk < 2; kk++) {
            const int k8 = kh * 2 + kk;
            float4 bf[8];
#pragma unroll
            for (int j = 0; j < 8; j++)
                bf[j] = *(const float4*)(sB + k8 * 4096 + j * 512 + lane * 16);

            uint32_t ahi[4], alo[4];
#pragma unroll
            for (int h = 0; h < 2; h++) {
                int row = rb + 8 * h + gid;
                float xa = sx[row * SXS + k8 * 8 + tig];
                float xb = sx[row * SXS + k8 * 8 + tig + 4];
                uint32_t h0 = tf32_bits(xa), h1 = tf32_bits(xb);
                ahi[h]     = h0;
                ahi[h + 2] = h1;
                alo[h]     = tf32_bits(xa - __uint_as_float(h0));
                alo[h + 2] = tf32_bits(xb - __uint_as_float(h1));
            }
#pragma unroll
            for (int j = 0; j < 8; j++) {
                uint32_t bh0 = __float_as_uint(bf[j].x), bh1 = __float_as_uint(bf[j].y);
                uint32_t bl0 = __float_as_uint(bf[j].z), bl1 = __float_as_uint(bf[j].w);
                mma_tf32(acc[j], ahi, bh0, bh1);
                mma_tf32(acc[j], ahi, bl0, bl1);
                mma_tf32(acc[j], alo, bh0, bh1);
            }
        }
    };

    issue_loads(0);
    issue_loads(1);
    for (int t = 0; t < NT; t++) {
        if (t < NT - 1) asm volatile("cp.async.wait_group 1;\n" ::: "memory");
        else            asm volatile("cp.async.wait_group 0;\n" ::: "memory");
        __syncthreads();
        compute_tile(t & 1);
        __syncthreads();
        if (t + 2 < NT) issue_loads(t + 2);
    }

    // K-half reduction into smem logits [64][68], + bias
    float* slog = (float*)smem;
    const float* sbias = (const float*)(smem + 2 * STAGE);
    if (kh == 1) {
#pragma unroll
        for (int j = 0; j < 8; j++) {
            int row = rb + gid;
            int col = j * 8 + 2 * tig;
            slog[row * 68 + col]           = acc[j][0];
            slog[row * 68 + col + 1]       = acc[j][1];
            slog[(row + 8) * 68 + col]     = acc[j][2];
            slog[(row + 8) * 68 + col + 1] = acc[j][3];
        }
    }
    __syncthreads();
    if (kh == 0) {
#pragma unroll
        for (int j = 0; j < 8; j++) {
            int row = rb + gid;
            int col = j * 8 + 2 * tig;
            slog[row * 68 + col]           += acc[j][0] + sbias[col];
            slog[row * 68 + col + 1]       += acc[j][1] + sbias[col + 1];
            slog[(row + 8) * 68 + col]     += acc[j][2] + sbias[col];
            slog[(row + 8) * 68 + col + 1] += acc[j][3] + sbias[col + 1];
        }
    }
    __syncthreads();

    // epilogue: one thread per row; top-4 + softmax; flag near-ties
    if (tid < BM) {
        const int r = tid;
        float d[64];
#pragma unroll
        for (int e4 = 0; e4 < 16; e4++) {
            float4 v = *(const float4*)(slog + r * 68 + e4 * 4);
            d[e4 * 4] = v.x; d[e4 * 4 + 1] = v.y; d[e4 * 4 + 2] = v.z; d[e4 * 4 + 3] = v.w;
        }
        float m1 = -1e30f, m2 = -1e30f, m3 = -1e30f, m4 = -1e30f;
        int i1 = 0, i2 = 0, i3 = 0, i4 = 0;
#pragma unroll
        for (int e = 0; e < 64; e++) {
            float v = d[e];
            if (v > m1)      { m4=m3;i4=i3; m3=m2;i3=i2; m2=m1;i2=i1; m1=v;i1=e; }
            else if (v > m2) { m4=m3;i4=i3; m3=m2;i3=i2; m2=v;i2=e; }
            else if (v > m3) { m4=m3;i4=i3; m3=v;i3=e; }
            else if (v > m4) { m4=v;i4=e; }
        }
        float s = 0.0f;
#pragma unroll
        for (int e = 0; e < 64; e++) s += __expf(d[e] - m1);
        float g1 = 1.0f / s;
        float g2 = __expf(m2 - m1) / s;

        float* orow = out_mask + (size_t)(row0 + r) * E_DIM;
#pragma unroll
        for (int e4 = 0; e4 < 16; e4++) {
            float4 v;
            int e = e4 * 4;
            v.x = (e     == i1) ? g1 : ((e     == i2) ? g2 : 0.0f);
            v.y = (e + 1 == i1) ? g1 : ((e + 1 == i2) ? g2 : 0.0f);
            v.z = (e + 2 == i1) ? g1 : ((e + 2 == i2) ? g2 : 0.0f);
            v.w = (e + 3 == i1) ? g1 : ((e + 3 == i2) ? g2 : 0.0f);
            *(float4*)(orow + e) = v;
        }
        if (write_idx) {
            float2 ix = make_float2((float)i1, (float)i2);
            *(float2*)(out_idx + (size_t)(row0 + r) * 2) = ix;
        }
        if ((m1 - m2 < TAU) || (m2 - m3 < TAU) || (m3 - m4 < TAU)) {
            int f = atomicAdd(&s_cnt, 1);
            if (f < MAXFLAG) {
                s_fr[f] = r;
                s_fc[f] = make_int4(i1, i2, i3, i4);
                s_fs[f] = s;
                s_fm[f] = m1;
            }
        }
    }
    __syncthreads();

    // rescue: one warp per flagged row; recompute the 4 candidate logits exactly
    int cnt = min(s_cnt, MAXFLAG);
    for (int f = wid; f < cnt; f += 8) {
        const int r = s_fr[f];
        const int4 c = s_fc[f];
        const float sden = s_fs[f], m1a = s_fm[f];
        const float* xr = x + (size_t)(row0 + r) * D_DIM;
        float a0 = 0.f, a1 = 0.f, a2 = 0.f, a3 = 0.f;
        for (int k = lane; k < D_DIM; k += 32) {
            float xv = xr[k];
            a0 = fmaf(xv, g_wk[(size_t)c.x * D_DIM + k], a0);
            a1 = fmaf(xv, g_wk[(size_t)c.y * D_DIM + k], a1);
            a2 = fmaf(xv, g_wk[(size_t)c.z * D_DIM + k], a2);
            a3 = fmaf(xv, g_wk[(size_t)c.w * D_DIM + k], a3);
        }
#pragma unroll
        for (int off = 16; off; off >>= 1) {
            a0 += __shfl_xor_sync(0xffffffffu, a0, off);
            a1 += __shfl_xor_sync(0xffffffffu, a1, off);
            a2 += __shfl_xor_sync(0xffffffffu, a2, off);
            a3 += __shfl_xor_sync(0xffffffffu, a3, off);
        }
        const float* sbias = (const float*)(smem + 2 * STAGE);
        float lv[4] = { a0 + sbias[c.x], a1 + sbias[c.y], a2 + sbias[c.z], a3 + sbias[c.w] };
        int   li[4] = { c.x, c.y, c.z, c.w };
#pragma unroll
        for (int p = 0; p < 3; p++)
#pragma unroll
            for (int q2 = 0; q2 < 3 - p; q2++) {
                bool sw = (lv[q2 + 1] > lv[q2]) ||
                          (lv[q2 + 1] == lv[q2] && li[q2 + 1] < li[q2]);
                if (sw) {
                    float tv = lv[q2]; lv[q2] = lv[q2 + 1]; lv[q2 + 1] = tv;
                    int  ti2 = li[q2]; li[q2] = li[q2 + 1]; li[q2 + 1] = ti2;
                }
            }
        float ng1 = __expf(lv[0] - m1a) / sden;
        float ng2 = __expf(lv[1] - m1a) / sden;
        int j1 = li[0], j2 = li[1];

        float* orow = out_mask + (size_t)(row0 + r) * E_DIM;
#pragma unroll
        for (int p = 0; p < 2; p++) {
            int e = lane + p * 32;
            orow[e] = (e == j1) ? ng1 : ((e == j2) ? ng2 : 0.0f);
        }
        if (write_idx && lane == 0) {
            float2 ix = make_float2((float)j1, (float)j2);
            *(float2*)(out_idx + (size_t)(row0 + r) * 2) = ix;
        }
    }
}

extern "C" void kernel_launch(void* const* d_in, const int* in_sizes, int n_in,
                              void* d_out, int out_size) {
    const float* x = (const float*)d_in[0];
    const float* W = (const float*)d_in[1];
    const float* b = (const float*)d_in[2];
    float* out     = (float*)d_out;
    float* out_idx = out + (size_t)N_ROWS * E_DIM;
    int write_idx  = (out_size >= N_ROWS * (E_DIM + 2)) ? 1 : 0;

    cudaFuncSetAttribute(router_main, cudaFuncAttributeMaxDynamicSharedMemorySize,
                         SMEM_TOTAL);
    wpack_kernel<<<256, 256>>>(W);
    router_main<<<N_ROWS / BM, THREADS, SMEM_TOTAL>>>(x, b, out, out_idx, write_idx);
}

// round 9
// speedup vs baseline: 1.5667x; 1.5667x over previous
#include <cuda_runtime.h>
#include <cuda_bf16.h>
#include <math.h>
#include <stdint.h>

#define N_ROWS 16384
#define D_DIM  2048
#define E_DIM  64
#define BM     64
#define KT     32
#define NT     (D_DIM / KT)        // 64
#define THREADS 128
#define SXS    36                  // x tile row stride (floats)
#define X_BYTES (BM * SXS * 4)     // 9216
#define B_BYTES 8192               // 2 k16-chunks x 8 j x 32 lanes x 16B
#define STAGE   (X_BYTES + B_BYTES) // 17408
#define NSTAGE 3
#define SMEM_TOTAL (NSTAGE * STAGE + 256)
#define TAU 5e-4f
#define MAXFLAG 64

__device__ __forceinline__ uint32_t smem_u32(const void* p) {
    return (uint32_t)__cvta_generic_to_shared(p);
}
__device__ __forceinline__ void cp_async16(uint32_t dst, const void* src) {
    asm volatile("cp.async.cg.shared.global [%0], [%1], 16;\n" :: "r"(dst), "l"(src));
}
// pack two bf16 (truncated high halves of two fp32) in one PRMT
__device__ __forceinline__ uint32_t prmt_hi(uint32_t a, uint32_t b) {
    uint32_t d; asm("prmt.b32 %0, %1, %2, 0x7632;" : "=r"(d) : "r"(a), "r"(b)); return d;
}
// pack bf16x2 with rounding; low half = lo
__device__ __forceinline__ uint32_t cvt_bf2(float lo, float hi) {
    uint32_t d; asm("cvt.rn.bf16x2.f32 %0, %1, %2;" : "=r"(d) : "f"(hi), "f"(lo)); return d;
}
__device__ __forceinline__ void mma_bf16(float* c, const uint32_t* a,
                                         uint32_t b0, uint32_t b1) {
    asm volatile(
        "mma.sync.aligned.m16n8k16.row.col.f32.bf16.bf16.f32 "
        "{%0,%1,%2,%3}, {%4,%5,%6,%7}, {%8,%9}, {%0,%1,%2,%3};"
        : "+f"(c[0]), "+f"(c[1]), "+f"(c[2]), "+f"(c[3])
        : "r"(a[0]), "r"(a[1]), "r"(a[2]), "r"(a[3]), "r"(b0), "r"(b1));
}

// B fragment-ready: [c(k16 chunk)][j][lane] -> uint4 {b0_hi, b1_hi, b0_lo, b1_lo}
__device__ uint4 g_wb[128 * 8 * 32];
// exact W, K-major: g_wk[e][k]
__device__ float g_wk[E_DIM * D_DIM];

__global__ void wpack_kernel(const float* __restrict__ W) {
    int idx = blockIdx.x * blockDim.x + threadIdx.x;   // 65536
    if (idx < 32768) {
        int lane = idx & 31, j = (idx >> 5) & 7, c = idx >> 8;
        int tig = lane & 3, gid = lane >> 2;
        int n = j * 8 + gid, k0 = c * 16;
        float w0 = W[(size_t)(k0 + 2 * tig)     * E_DIM + n];
        float w1 = W[(size_t)(k0 + 2 * tig + 1) * E_DIM + n];
        float w2 = W[(size_t)(k0 + 2 * tig + 8) * E_DIM + n];
        float w3 = W[(size_t)(k0 + 2 * tig + 9) * E_DIM + n];
        uint32_t u0 = __float_as_uint(w0), u1 = __float_as_uint(w1);
        uint32_t u2 = __float_as_uint(w2), u3 = __float_as_uint(w3);
        uint4 v;
        v.x = prmt_hi(u0, u1);
        v.y = prmt_hi(u2, u3);
        v.z = cvt_bf2(w0 - __uint_as_float(u0 & 0xFFFF0000u),
                      w1 - __uint_as_float(u1 & 0xFFFF0000u));
        v.w = cvt_bf2(w2 - __uint_as_float(u2 & 0xFFFF0000u),
                      w3 - __uint_as_float(u3 & 0xFFFF0000u));
        g_wb[idx] = v;
    }
    {   // exact copy, coalesced writes
        int e  = idx >> 10;            // 0..63
        int k2 = (idx & 1023) * 2;     // 0..2046
        g_wk[(size_t)e * D_DIM + k2]     = W[(size_t)k2 * E_DIM + e];
        g_wk[(size_t)e * D_DIM + k2 + 1] = W[(size_t)(k2 + 1) * E_DIM + e];
    }
}

__global__ __launch_bounds__(THREADS, 4)
void router_main(const float* __restrict__ x,
                 const float* __restrict__ bias,
                 float* __restrict__ out_mask,
                 float* __restrict__ out_idx,
                 int write_idx)
{
    extern __shared__ char smem[];
    __shared__ int   s_cnt;
    __shared__ int   s_fr[MAXFLAG];
    __shared__ int4  s_fc[MAXFLAG];
    __shared__ float s_fs[MAXFLAG];
    __shared__ float s_fm[MAXFLAG];

    const uint32_t sb = smem_u32(smem);
    const int tid  = threadIdx.x;
    const int wid  = tid >> 5;
    const int lane = tid & 31;
    const int gid  = lane >> 2;
    const int tig  = lane & 3;
    const int rbw  = (wid & 1) * 32;   // warp row block (M=32)
    const int kh   = wid >> 1;         // k16 chunk within tile
    const int row0 = blockIdx.x * BM;

    if (tid < E_DIM) ((float*)(smem + NSTAGE * STAGE))[tid] = bias[tid];
    if (tid == 0) s_cnt = 0;

    float acc[2][8][4];
#pragma unroll
    for (int mt = 0; mt < 2; mt++)
#pragma unroll
        for (int j = 0; j < 8; j++)
#pragma unroll
            for (int q = 0; q < 4; q++) acc[mt][j][q] = 0.0f;

    auto issue_loads = [&](int t) {
        const int s = t % NSTAGE;
#pragma unroll
        for (int p = 0; p < 4; p++) {               // x: 64 rows x 8 float4
            int id = tid + p * THREADS;
            int r = id >> 3, c4 = id & 7;
            cp_async16(sb + s * STAGE + r * (SXS * 4) + c4 * 16,
                       x + (size_t)(row0 + r) * D_DIM + t * KT + c4 * 4);
        }
#pragma unroll
        for (int p = 0; p < 4; p++) {               // B: contiguous 8KB
            int id = tid + p * THREADS;
            cp_async16(sb + s * STAGE + X_BYTES + id * 16,
                       (const char*)g_wb + (size_t)t * B_BYTES + id * 16);
        }
        asm volatile("cp.async.commit_group;\n");
    };

    auto compute_tile = [&](int s) {
        const float* sx = (const float*)(smem + s * STAGE);
        const char*  sB = smem + s * STAGE + X_BYTES;
        const int kb = kh * 16;

        uint32_t ahi[2][4], alo[2][4];
#pragma unroll
        for (int mt = 0; mt < 2; mt++) {
            const float* ap = sx + (rbw + mt * 16 + gid) * SXS + kb + 2 * tig;
            float2 v00 = *(const float2*)ap;
            float2 v10 = *(const float2*)(ap + 8 * SXS);
            float2 v01 = *(const float2*)(ap + 8);
            float2 v11 = *(const float2*)(ap + 8 * SXS + 8);
            uint32_t u;
            float2 v;
            v = v00; u = __float_as_uint(v.x);
            ahi[mt][0] = prmt_hi(u, __float_as_uint(v.y));
            alo[mt][0] = cvt_bf2(v.x - __uint_as_float(u & 0xFFFF0000u),
                                 v.y - __uint_as_float(__float_as_uint(v.y) & 0xFFFF0000u));
            v = v10; u = __float_as_uint(v.x);
            ahi[mt][1] = prmt_hi(u, __float_as_uint(v.y));
            alo[mt][1] = cvt_bf2(v.x - __uint_as_float(u & 0xFFFF0000u),
                                 v.y - __uint_as_float(__float_as_uint(v.y) & 0xFFFF0000u));
            v = v01; u = __float_as_uint(v.x);
            ahi[mt][2] = prmt_hi(u, __float_as_uint(v.y));
            alo[mt][2] = cvt_bf2(v.x - __uint_as_float(u & 0xFFFF0000u),
                                 v.y - __uint_as_float(__float_as_uint(v.y) & 0xFFFF0000u));
            v = v11; u = __float_as_uint(v.x);
            ahi[mt][3] = prmt_hi(u, __float_as_uint(v.y));
            alo[mt][3] = cvt_bf2(v.x - __uint_as_float(u & 0xFFFF0000u),
                                 v.y - __uint_as_float(__float_as_uint(v.y) & 0xFFFF0000u));
        }

#pragma unroll
        for (int half = 0; half < 2; half++) {
            uint4 bf[4];
#pragma unroll
            for (int jj = 0; jj < 4; jj++)
                bf[jj] = *(const uint4*)(sB + kh * 4096 + (half * 4 + jj) * 512 + lane * 16);
#pragma unroll
            for (int jj = 0; jj < 4; jj++) {
                int j = half * 4 + jj;
#pragma unroll
                for (int mt = 0; mt < 2; mt++) {
                    mma_bf16(acc[mt][j], ahi[mt], bf[jj].x, bf[jj].y);
                    mma_bf16(acc[mt][j], ahi[mt], bf[jj].z, bf[jj].w);
                    mma_bf16(acc[mt][j], alo[mt], bf[jj].x, bf[jj].y);
                }
            }
        }
    };

    issue_loads(0);
    issue_loads(1);
    for (int t = 0; t < NT; t++) {
        if (t < NT - 1) asm volatile("cp.async.wait_group 1;\n" ::: "memory");
        else            asm volatile("cp.async.wait_group 0;\n" ::: "memory");
        __syncthreads();
        if (t + 2 < NT) issue_loads(t + 2);
        compute_tile(t % NSTAGE);   // 3-stage ring: slot (t+2)%3 never aliases slot t or t+1
    }
    __syncthreads();

    // K-chunk reduction into smem logits [64][68], + bias
    float* slog = (float*)smem;
    const float* sbias = (const float*)(smem + NSTAGE * STAGE);
    if (kh == 1) {
#pragma unroll
        for (int mt = 0; mt < 2; mt++)
#pragma unroll
            for (int j = 0; j < 8; j++) {
                int row = rbw + mt * 16 + gid;
                int col = j * 8 + 2 * tig;
                slog[row * 68 + col]           = acc[mt][j][0];
                slog[row * 68 + col + 1]       = acc[mt][j][1];
                slog[(row + 8) * 68 + col]     = acc[mt][j][2];
                slog[(row + 8) * 68 + col + 1] = acc[mt][j][3];
            }
    }
    __syncthreads();
    if (kh == 0) {
#pragma unroll
        for (int mt = 0; mt < 2; mt++)
#pragma unroll
            for (int j = 0; j < 8; j++) {
                int row = rbw + mt * 16 + gid;
                int col = j * 8 + 2 * tig;
                slog[row * 68 + col]           += acc[mt][j][0] + sbias[col];
                slog[row * 68 + col + 1]       += acc[mt][j][1] + sbias[col + 1];
                slog[(row + 8) * 68 + col]     += acc[mt][j][2] + sbias[col];
                slog[(row + 8) * 68 + col + 1] += acc[mt][j][3] + sbias[col + 1];
            }
    }
    __syncthreads();

    // epilogue: one thread per row; top-4 + softmax; flag near-ties
    if (tid < BM) {
        const int r = tid;
        float d[64];
#pragma unroll
        for (int e4 = 0; e4 < 16; e4++) {
            float4 v = *(const float4*)(slog + r * 68 + e4 * 4);
            d[e4 * 4] = v.x; d[e4 * 4 + 1] = v.y; d[e4 * 4 + 2] = v.z; d[e4 * 4 + 3] = v.w;
        }
        float m1 = -1e30f, m2 = -1e30f, m3 = -1e30f, m4 = -1e30f;
        int i1 = 0, i2 = 0, i3 = 0, i4 = 0;
#pragma unroll
        for (int e = 0; e < 64; e++) {
            float v = d[e];
            if (v > m1)      { m4=m3;i4=i3; m3=m2;i3=i2; m2=m1;i2=i1; m1=v;i1=e; }
            else if (v > m2) { m4=m3;i4=i3; m3=m2;i3=i2; m2=v;i2=e; }
            else if (v > m3) { m4=m3;i4=i3; m3=v;i3=e; }
            else if (v > m4) { m4=v;i4=e; }
        }
        float s = 0.0f;
#pragma unroll
        for (int e = 0; e < 64; e++) s += __expf(d[e] - m1);
        float g1 = 1.0f / s;
        float g2 = __expf(m2 - m1) / s;

        float* orow = out_mask + (size_t)(row0 + r) * E_DIM;
#pragma unroll
        for (int e4 = 0; e4 < 16; e4++) {
            float4 v;
            int e = e4 * 4;
            v.x = (e     == i1) ? g1 : ((e     == i2) ? g2 : 0.0f);
            v.y = (e + 1 == i1) ? g1 : ((e + 1 == i2) ? g2 : 0.0f);
            v.z = (e + 2 == i1) ? g1 : ((e + 2 == i2) ? g2 : 0.0f);
            v.w = (e + 3 == i1) ? g1 : ((e + 3 == i2) ? g2 : 0.0f);
            *(float4*)(orow + e) = v;
        }
        if (write_idx) {
            float2 ix = make_float2((float)i1, (float)i2);
            *(float2*)(out_idx + (size_t)(row0 + r) * 2) = ix;
        }
        if ((m1 - m2 < TAU) || (m2 - m3 < TAU) || (m3 - m4 < TAU)) {
            int f = atomicAdd(&s_cnt, 1);
            if (f < MAXFLAG) {
                s_fr[f] = r;
                s_fc[f] = make_int4(i1, i2, i3, i4);
                s_fs[f] = s;
                s_fm[f] = m1;
            }
        }
    }
    __syncthreads();

    // rescue: one warp per flagged row; recompute 4 candidate logits exactly in fp32
    int cnt = min(s_cnt, MAXFLAG);
    for (int f = wid; f < cnt; f += 4) {
        const int r = s_fr[f];
        const int4 c = s_fc[f];
        const float sden = s_fs[f], m1a = s_fm[f];
        const float* xr = x + (size_t)(row0 + r) * D_DIM;
        float a0 = 0.f, a1 = 0.f, a2 = 0.f, a3 = 0.f;
        for (int k = lane; k < D_DIM; k += 32) {
            float xv = xr[k];
            a0 = fmaf(xv, g_wk[(size_t)c.x * D_DIM + k], a0);
            a1 = fmaf(xv, g_wk[(size_t)c.y * D_DIM + k], a1);
            a2 = fmaf(xv, g_wk[(size_t)c.z * D_DIM + k], a2);
            a3 = fmaf(xv, g_wk[(size_t)c.w * D_DIM + k], a3);
        }
#pragma unroll
        for (int off = 16; off; off >>= 1) {
            a0 += __shfl_xor_sync(0xffffffffu, a0, off);
            a1 += __shfl_xor_sync(0xffffffffu, a1, off);
            a2 += __shfl_xor_sync(0xffffffffu, a2, off);
            a3 += __shfl_xor_sync(0xffffffffu, a3, off);
        }
        float lv[4] = { a0 + sbias[c.x], a1 + sbias[c.y], a2 + sbias[c.z], a3 + sbias[c.w] };
        int   li[4] = { c.x, c.y, c.z, c.w };
#pragma unroll
        for (int p = 0; p < 3; p++)
#pragma unroll
            for (int q2 = 0; q2 < 3 - p; q2++) {
                bool sw = (lv[q2 + 1] > lv[q2]) ||
                          (lv[q2 + 1] == lv[q2] && li[q2 + 1] < li[q2]);
                if (sw) {
                    float tv = lv[q2]; lv[q2] = lv[q2 + 1]; lv[q2 + 1] = tv;
                    int  ti2 = li[q2]; li[q2] = li[q2 + 1]; li[q2 + 1] = ti2;
                }
            }
        float ng1 = __expf(lv[0] - m1a) / sden;
        float ng2 = __expf(lv[1] - m1a) / sden;
        int j1 = li[0], j2 = li[1];

        float* orow = out_mask + (size_t)(row0 + r) * E_DIM;
#pragma unroll
        for (int p = 0; p < 2; p++) {
            int e = lane + p * 32;
            orow[e] = (e == j1) ? ng1 : ((e == j2) ? ng2 : 0.0f);
        }
        if (write_idx && lane == 0) {
            float2 ix = make_float2((float)j1, (float)j2);
            *(float2*)(out_idx + (size_t)(row0 + r) * 2) = ix;
        }
    }
}

extern "C" void kernel_launch(void* const* d_in, const int* in_sizes, int n_in,
                              void* d_out, int out_size) {
    const float* x = (const float*)d_in[0];
    const float* W = (const float*)d_in[1];
    const float* b = (const float*)d_in[2];
    float* out     = (float*)d_out;
    float* out_idx = out + (size_t)N_ROWS * E_DIM;
    int write_idx  = (out_size >= N_ROWS * (E_DIM + 2)) ? 1 : 0;

    cudaFuncSetAttribute(router_main, cudaFuncAttributeMaxDynamicSharedMemorySize,
                         SMEM_TOTAL);
    wpack_kernel<<<256, 256>>>(W);
    router_main<<<N_ROWS / BM, THREADS, SMEM_TOTAL>>>(x, b, out, out_idx, write_idx);
}

// round 11
// speedup vs baseline: 1.5674x; 1.0004x over previous
#include <cuda_runtime.h>
#include <cuda_bf16.h>
#include <math.h>
#include <stdint.h>

#define N_ROWS 16384
#define D_DIM  2048
#define E_DIM  64
#define BM     64
#define KT     32
#define NT     (D_DIM / KT)        // 64
#define NP     (NT / 2)            // 32 tile pairs
#define THREADS 256
#define SXS    36                  // x tile row stride (floats)
#define X_BYTES (BM * SXS * 4)     // 9216
#define B_BYTES 8192               // 2 k16-chunks x 8 j x 32 lanes x 16B
#define STAGE   (X_BYTES + B_BYTES) // 17408
#define NSTAGE 6
#define SMEM_TOTAL (NSTAGE * STAGE + 256)   // 104704
#define TAU 5e-4f
#define MAXFLAG 64

__device__ __forceinline__ uint32_t smem_u32(const void* p) {
    return (uint32_t)__cvta_generic_to_shared(p);
}
__device__ __forceinline__ void cp_async16(uint32_t dst, const void* src) {
    asm volatile("cp.async.cg.shared.global [%0], [%1], 16;\n" :: "r"(dst), "l"(src));
}
__device__ __forceinline__ uint32_t prmt_hi(uint32_t a, uint32_t b) {
    uint32_t d; asm("prmt.b32 %0, %1, %2, 0x7632;" : "=r"(d) : "r"(a), "r"(b)); return d;
}
__device__ __forceinline__ uint32_t cvt_bf2(float lo, float hi) {
    uint32_t d; asm("cvt.rn.bf16x2.f32 %0, %1, %2;" : "=r"(d) : "f"(hi), "f"(lo)); return d;
}
__device__ __forceinline__ void mma_bf16(float* c, const uint32_t* a,
                                         uint32_t b0, uint32_t b1) {
    asm volatile(
        "mma.sync.aligned.m16n8k16.row.col.f32.bf16.bf16.f32 "
        "{%0,%1,%2,%3}, {%4,%5,%6,%7}, {%8,%9}, {%0,%1,%2,%3};"
        : "+f"(c[0]), "+f"(c[1]), "+f"(c[2]), "+f"(c[3])
        : "r"(a[0]), "r"(a[1]), "r"(a[2]), "r"(a[3]), "r"(b0), "r"(b1));
}

// B fragment-ready: [c(k16 chunk)][j][lane] -> uint4 {b0_hi, b1_hi, b0_lo, b1_lo}
__device__ uint4 g_wb[128 * 8 * 32];
// exact W, K-major: g_wk[e][k]
__device__ float g_wk[E_DIM * D_DIM];

__global__ void wpack_kernel(const float* __restrict__ W) {
    int idx = blockIdx.x * blockDim.x + threadIdx.x;   // 65536
    if (idx < 32768) {
        int lane = idx & 31, j = (idx >> 5) & 7, c = idx >> 8;
        int tig = lane & 3, gid = lane >> 2;
        int n = j * 8 + gid, k0 = c * 16;
        float w0 = W[(size_t)(k0 + 2 * tig)     * E_DIM + n];
        float w1 = W[(size_t)(k0 + 2 * tig + 1) * E_DIM + n];
        float w2 = W[(size_t)(k0 + 2 * tig + 8) * E_DIM + n];
        float w3 = W[(size_t)(k0 + 2 * tig + 9) * E_DIM + n];
        uint32_t u0 = __float_as_uint(w0), u1 = __float_as_uint(w1);
        uint32_t u2 = __float_as_uint(w2), u3 = __float_as_uint(w3);
        uint4 v;
        v.x = prmt_hi(u0, u1);
        v.y = prmt_hi(u2, u3);
        v.z = cvt_bf2(w0 - __uint_as_float(u0 & 0xFFFF0000u),
                      w1 - __uint_as_float(u1 & 0xFFFF0000u));
        v.w = cvt_bf2(w2 - __uint_as_float(u2 & 0xFFFF0000u),
                      w3 - __uint_as_float(u3 & 0xFFFF0000u));
        g_wb[idx] = v;
    }
    {   // exact copy, coalesced writes
        int e  = idx >> 10;
        int k2 = (idx & 1023) * 2;
        g_wk[(size_t)e * D_DIM + k2]     = W[(size_t)k2 * E_DIM + e];
        g_wk[(size_t)e * D_DIM + k2 + 1] = W[(size_t)(k2 + 1) * E_DIM + e];
    }
}

__global__ __launch_bounds__(THREADS, 2)
void router_main(const float* __restrict__ x,
                 const float* __restrict__ bias,
                 float* __restrict__ out_mask,
                 float* __restrict__ out_idx,
                 int write_idx)
{
    extern __shared__ char smem[];
    __shared__ int   s_cnt;
    __shared__ int   s_fr[MAXFLAG];
    __shared__ int4  s_fc[MAXFLAG];
    __shared__ float s_fs[MAXFLAG];
    __shared__ float s_fm[MAXFLAG];

    const uint32_t sb = smem_u32(smem);
    const int tid  = threadIdx.x;
    const int wid  = tid >> 5;
    const int lane = tid & 31;
    const int gid  = lane >> 2;
    const int tig  = lane & 3;
    const int rbw  = (wid & 1) * 32;   // warp row block (M=32)
    const int kh   = (wid >> 1) & 1;   // k16 chunk within tile
    const int par  = wid >> 2;         // tile parity within pair
    const int row0 = blockIdx.x * BM;

    if (tid < E_DIM) ((float*)(smem + NSTAGE * STAGE))[tid] = bias[tid];
    if (tid == 0) s_cnt = 0;

    float acc[2][8][4];
#pragma unroll
    for (int mt = 0; mt < 2; mt++)
#pragma unroll
        for (int j = 0; j < 8; j++)
#pragma unroll
            for (int q = 0; q < 4; q++) acc[mt][j][q] = 0.0f;

    auto issue_pair = [&](int tp) {
        const int s0 = (tp % 3) * 2;
#pragma unroll
        for (int sub = 0; sub < 2; sub++) {
            const int t = 2 * tp + sub;
            const uint32_t base = sb + (s0 + sub) * STAGE;
#pragma unroll
            for (int p = 0; p < 2; p++) {           // x: 64 rows x 8 float4
                int id = tid + p * THREADS;
                int r = id >> 3, c4 = id & 7;
                cp_async16(base + r * (SXS * 4) + c4 * 16,
                           x + (size_t)(row0 + r) * D_DIM + t * KT + c4 * 4);
            }
#pragma unroll
            for (int p = 0; p < 2; p++) {           // B: contiguous 8KB
                int id = tid + p * THREADS;
                cp_async16(base + X_BYTES + id * 16,
                           (const char*)g_wb + (size_t)t * B_BYTES + id * 16);
            }
        }
        asm volatile("cp.async.commit_group;\n");
    };

    auto compute_tile = [&](int s) {
        const float* sx = (const float*)(smem + s * STAGE);
        const char*  sB = smem + s * STAGE + X_BYTES;
        const int kb = kh * 16;

        uint32_t ahi[2][4], alo[2][4];
#pragma unroll
        for (int mt = 0; mt < 2; mt++) {
            const float* ap = sx + (rbw + mt * 16 + gid) * SXS + kb + 2 * tig;
            float2 vv[4];
            vv[0] = *(const float2*)ap;
            vv[1] = *(const float2*)(ap + 8 * SXS);
            vv[2] = *(const float2*)(ap + 8);
            vv[3] = *(const float2*)(ap + 8 * SXS + 8);
#pragma unroll
            for (int q = 0; q < 4; q++) {
                uint32_t ux = __float_as_uint(vv[q].x);
                uint32_t uy = __float_as_uint(vv[q].y);
                ahi[mt][q] = prmt_hi(ux, uy);
                alo[mt][q] = cvt_bf2(vv[q].x - __uint_as_float(ux & 0xFFFF0000u),
                                     vv[q].y - __uint_as_float(uy & 0xFFFF0000u));
            }
        }

#pragma unroll
        for (int half = 0; half < 2; half++) {
            uint4 bf[4];
#pragma unroll
            for (int jj = 0; jj < 4; jj++)
                bf[jj] = *(const uint4*)(sB + kh * 4096 + (half * 4 + jj) * 512 + lane * 16);
#pragma unroll
            for (int jj = 0; jj < 4; jj++) {
                int j = half * 4 + jj;
#pragma unroll
                for (int mt = 0; mt < 2; mt++) {
                    mma_bf16(acc[mt][j], ahi[mt], bf[jj].x, bf[jj].y);
                    mma_bf16(acc[mt][j], ahi[mt], bf[jj].z, bf[jj].w);
                    mma_bf16(acc[mt][j], alo[mt], bf[jj].x, bf[jj].y);
                }
            }
        }
    };

    issue_pair(0);
    issue_pair(1);
    for (int tp = 0; tp < NP; tp++) {
        if (tp < NP - 1) asm volatile("cp.async.wait_group 1;\n" ::: "memory");
        else             asm volatile("cp.async.wait_group 0;\n" ::: "memory");
        __syncthreads();   // pair tp ready; pair tp-1 compute finished on all warps
        if (tp + 2 < NP) issue_pair(tp + 2);
        compute_tile((tp % 3) * 2 + par);   // even-parity warps: tile 2tp; odd: 2tp+1
    }
    __syncthreads();

    // 4-way partial reduction (par x kh) into smem logits [64][68], + bias
    float* slog = (float*)smem;
    const float* sbias = (const float*)(smem + NSTAGE * STAGE);
    const int grp = wid >> 1;            // par*2 + kh: 3,2,1,0 phases
#pragma unroll
    for (int phase = 3; phase >= 0; phase--) {
        if (grp == phase) {
#pragma unroll
            for (int mt = 0; mt < 2; mt++)
#pragma unroll
                for (int j = 0; j < 8; j++) {
                    int row = rbw + mt * 16 + gid;
                    int col = j * 8 + 2 * tig;
                    if (phase == 3) {
                        slog[row * 68 + col]           = acc[mt][j][0];
                        slog[row * 68 + col + 1]       = acc[mt][j][1];
                        slog[(row + 8) * 68 + col]     = acc[mt][j][2];
                        slog[(row + 8) * 68 + col + 1] = acc[mt][j][3];
                    } else if (phase > 0) {
                        slog[row * 68 + col]           += acc[mt][j][0];
                        slog[row * 68 + col + 1]       += acc[mt][j][1];
                        slog[(row + 8) * 68 + col]     += acc[mt][j][2];
                        slog[(row + 8) * 68 + col + 1] += acc[mt][j][3];
                    } else {
                        slog[row * 68 + col]           += acc[mt][j][0] + sbias[col];
                        slog[row * 68 + col + 1]       += acc[mt][j][1] + sbias[col + 1];
                        slog[(row + 8) * 68 + col]     += acc[mt][j][2] + sbias[col];
                        slog[(row + 8) * 68 + col + 1] += acc[mt][j][3] + sbias[col + 1];
                    }
                }
        }
        __syncthreads();
    }

    // epilogue: one thread per row; top-4 + softmax; flag near-ties
    if (tid < BM) {
        const int r = tid;
        float d[64];
#pragma unroll
        for (int e4 = 0; e4 < 16; e4++) {
            float4 v = *(const float4*)(slog + r * 68 + e4 * 4);
            d[e4 * 4] = v.x; d[e4 * 4 + 1] = v.y; d[e4 * 4 + 2] = v.z; d[e4 * 4 + 3] = v.w;
        }
        float m1 = -1e30f, m2 = -1e30f, m3 = -1e30f, m4 = -1e30f;
        int i1 = 0, i2 = 0, i3 = 0, i4 = 0;
#pragma unroll
        for (int e = 0; e < 64; e++) {
            float v = d[e];
            if (v > m1)      { m4=m3;i4=i3; m3=m2;i3=i2; m2=m1;i2=i1; m1=v;i1=e; }
            else if (v > m2) { m4=m3;i4=i3; m3=m2;i3=i2; m2=v;i2=e; }
            else if (v > m3) { m4=m3;i4=i3; m3=v;i3=e; }
            else if (v > m4) { m4=v;i4=e; }
        }
        float s = 0.0f;
#pragma unroll
        for (int e = 0; e < 64; e++) s += __expf(d[e] - m1);
        float g1 = 1.0f / s;
        float g2 = __expf(m2 - m1) / s;

        float* orow = out_mask + (size_t)(row0 + r) * E_DIM;
#pragma unroll
        for (int e4 = 0; e4 < 16; e4++) {
            float4 v;
            int e = e4 * 4;
            v.x = (e     == i1) ? g1 : ((e     == i2) ? g2 : 0.0f);
            v.y = (e + 1 == i1) ? g1 : ((e + 1 == i2) ? g2 : 0.0f);
            v.z = (e + 2 == i1) ? g1 : ((e + 2 == i2) ? g2 : 0.0f);
            v.w = (e + 3 == i1) ? g1 : ((e + 3 == i2) ? g2 : 0.0f);
            *(float4*)(orow + e) = v;
        }
        if (write_idx) {
            float2 ix = make_float2((float)i1, (float)i2);
            *(float2*)(out_idx + (size_t)(row0 + r) * 2) = ix;
        }
        if ((m1 - m2 < TAU) || (m2 - m3 < TAU) || (m3 - m4 < TAU)) {
            int f = atomicAdd(&s_cnt, 1);
            if (f < MAXFLAG) {
                s_fr[f] = r;
                s_fc[f] = make_int4(i1, i2, i3, i4);
                s_fs[f] = s;
                s_fm[f] = m1;
            }
        }
    }
    __syncthreads();

    // rescue: one warp per flagged row; recompute 4 candidate logits exactly in fp32
    int cnt = min(s_cnt, MAXFLAG);
    for (int f = wid; f < cnt; f += 8) {
        const int r = s_fr[f];
        const int4 c = s_fc[f];
        const float sden = s_fs[f], m1a = s_fm[f];
        const float* xr = x + (size_t)(row0 + r) * D_DIM;
        float a0 = 0.f, a1 = 0.f, a2 = 0.f, a3 = 0.f;
        for (int k = lane; k < D_DIM; k += 32) {
            float xv = xr[k];
            a0 = fmaf(xv, g_wk[(size_t)c.x * D_DIM + k], a0);
            a1 = fmaf(xv, g_wk[(size_t)c.y * D_DIM + k], a1);
            a2 = fmaf(xv, g_wk[(size_t)c.z * D_DIM + k], a2);
            a3 = fmaf(xv, g_wk[(size_t)c.w * D_DIM + k], a3);
        }
#pragma unroll
        for (int off = 16; off; off >>= 1) {
            a0 += __shfl_xor_sync(0xffffffffu, a0, off);
            a1 += __shfl_xor_sync(0xffffffffu, a1, off);
            a2 += __shfl_xor_sync(0xffffffffu, a2, off);
            a3 += __shfl_xor_sync(0xffffffffu, a3, off);
        }
        const float* sbias2 = (const float*)(smem + NSTAGE * STAGE);
        float lv[4] = { a0 + sbias2[c.x], a1 + sbias2[c.y], a2 + sbias2[c.z], a3 + sbias2[c.w] };
        int   li[4] = { c.x, c.y, c.z, c.w };
#pragma unroll
        for (int p = 0; p < 3; p++)
#pragma unroll
            for (int q2 = 0; q2 < 3 - p; q2++) {
                bool sw = (lv[q2 + 1] > lv[q2]) ||
                          (lv[q2 + 1] == lv[q2] && li[q2 + 1] < li[q2]);
                if (sw) {
                    float tv = lv[q2]; lv[q2] = lv[q2 + 1]; lv[q2 + 1] = tv;
                    int  ti2 = li[q2]; li[q2] = li[q2 + 1]; li[q2 + 1] = ti2;
                }
            }
        float ng1 = __expf(lv[0] - m1a) / sden;
        float ng2 = __expf(lv[1] - m1a) / sden;
        int j1 = li[0], j2 = li[1];

        float* orow = out_mask + (size_t)(row0 + r) * E_DIM;
#pragma unroll
        for (int p = 0; p < 2; p++) {
            int e = lane + p * 32;
            orow[e] = (e == j1) ? ng1 : ((e == j2) ? ng2 : 0.0f);
        }
        if (write_idx && lane == 0) {
            float2 ix = make_float2((float)j1, (float)j2);
            *(float2*)(out_idx + (size_t)(row0 + r) * 2) = ix;
        }
    }
}

extern "C" void kernel_launch(void* const* d_in, const int* in_sizes, int n_in,
                              void* d_out, int out_size) {
    const float* x = (const float*)d_in[0];
    const float* W = (const float*)d_in[1];
    const float* b = (const float*)d_in[2];
    float* out     = (float*)d_out;
    float* out_idx = out + (size_t)N_ROWS * E_DIM;
    int write_idx  = (out_size >= N_ROWS * (E_DIM + 2)) ? 1 : 0;

    cudaFuncSetAttribute(router_main, cudaFuncAttributeMaxDynamicSharedMemorySize,
                         SMEM_TOTAL);
    wpack_kernel<<<256, 256>>>(W);
    router_main<<<N_ROWS / BM, THREADS, SMEM_TOTAL>>>(x, b, out, out_idx, write_idx);
}

// round 12
// speedup vs baseline: 1.6340x; 1.0425x over previous
#include <cuda_runtime.h>
#include <math.h>
#include <stdint.h>

#define N_ROWS 16384
#define D_DIM  2048
#define E_DIM  64
#define BM     64
#define KT     32
#define NT     (D_DIM / KT)        // 64
#define NPW    (NT / 2)            // 32 tiles per warp (parity split)
#define THREADS 256
#define TAU 5e-4f
#define MAXFLAG 64

__device__ __forceinline__ uint32_t prmt_hi(uint32_t a, uint32_t b) {
    uint32_t d; asm("prmt.b32 %0, %1, %2, 0x7632;" : "=r"(d) : "r"(a), "r"(b)); return d;
}
__device__ __forceinline__ uint32_t cvt_bf2(float lo, float hi) {
    uint32_t d; asm("cvt.rn.bf16x2.f32 %0, %1, %2;" : "=r"(d) : "f"(hi), "f"(lo)); return d;
}
__device__ __forceinline__ void mma_bf16(float* c, const uint32_t* a,
                                         uint32_t b0, uint32_t b1) {
    asm volatile(
        "mma.sync.aligned.m16n8k16.row.col.f32.bf16.bf16.f32 "
        "{%0,%1,%2,%3}, {%4,%5,%6,%7}, {%8,%9}, {%0,%1,%2,%3};"
        : "+f"(c[0]), "+f"(c[1]), "+f"(c[2]), "+f"(c[3])
        : "r"(a[0]), "r"(a[1]), "r"(a[2]), "r"(a[3]), "r"(b0), "r"(b1));
}

// B fragment-ready: linear index c*256 + j*32 + lane (c = 2t + kh), uint4
// = {b0_hi, b1_hi, b0_lo, b1_lo}
__device__ uint4 g_wb[128 * 8 * 32];
// exact W, K-major: g_wk[e][k]
__device__ float g_wk[E_DIM * D_DIM];

__global__ void wpack_kernel(const float* __restrict__ W) {
    int idx = blockIdx.x * blockDim.x + threadIdx.x;   // 65536
    if (idx < 32768) {
        int lane = idx & 31, j = (idx >> 5) & 7, c = idx >> 8;
        int tig = lane & 3, gid = lane >> 2;
        int n = j * 8 + gid, k0 = c * 16;
        float w0 = W[(size_t)(k0 + 2 * tig)     * E_DIM + n];
        float w1 = W[(size_t)(k0 + 2 * tig + 1) * E_DIM + n];
        float w2 = W[(size_t)(k0 + 2 * tig + 8) * E_DIM + n];
        float w3 = W[(size_t)(k0 + 2 * tig + 9) * E_DIM + n];
        uint32_t u0 = __float_as_uint(w0), u1 = __float_as_uint(w1);
        uint32_t u2 = __float_as_uint(w2), u3 = __float_as_uint(w3);
        uint4 v;
        v.x = prmt_hi(u0, u1);
        v.y = prmt_hi(u2, u3);
        v.z = cvt_bf2(w0 - __uint_as_float(u0 & 0xFFFF0000u),
                      w1 - __uint_as_float(u1 & 0xFFFF0000u));
        v.w = cvt_bf2(w2 - __uint_as_float(u2 & 0xFFFF0000u),
                      w3 - __uint_as_float(u3 & 0xFFFF0000u));
        g_wb[idx] = v;
    }
    {   // exact copy, coalesced writes
        int e  = idx >> 10;
        int k2 = (idx & 1023) * 2;
        g_wk[(size_t)e * D_DIM + k2]     = W[(size_t)k2 * E_DIM + e];
        g_wk[(size_t)e * D_DIM + k2 + 1] = W[(size_t)(k2 + 1) * E_DIM + e];
    }
}

__global__ __launch_bounds__(THREADS, 2)
void router_main(const float* __restrict__ x,
                 const float* __restrict__ bias,
                 float* __restrict__ out_mask,
                 float* __restrict__ out_idx,
                 int write_idx)
{
    __shared__ float slog[BM * 68];
    __shared__ float sbias[E_DIM];
    __shared__ int   s_cnt;
    __shared__ int   s_fr[MAXFLAG];
    __shared__ int4  s_fc[MAXFLAG];
    __shared__ float s_fs[MAXFLAG];
    __shared__ float s_fm[MAXFLAG];

    const int tid  = threadIdx.x;
    const int wid  = tid >> 5;
    const int lane = tid & 31;
    const int gid  = lane >> 2;
    const int tig  = lane & 3;
    const int rbw  = (wid & 1) * 32;   // warp row block (M=32)
    const int kh   = (wid >> 1) & 1;   // k16 chunk within tile
    const int par  = wid >> 2;         // tile parity
    const int row0 = blockIdx.x * BM;

    if (tid < E_DIM) sbias[tid] = bias[tid];
    if (tid == 0) s_cnt = 0;

    // per-thread x row pointers [mt][h], col offset kh*16 + 2*tig baked in
    const float* xp[2][2];
#pragma unroll
    for (int mt = 0; mt < 2; mt++)
#pragma unroll
        for (int h = 0; h < 2; h++)
            xp[mt][h] = x + (size_t)(row0 + rbw + mt * 16 + 8 * h + gid) * D_DIM
                          + kh * 16 + 2 * tig;

    const uint4* bp = g_wb + kh * 256 + lane;   // + t*512 + j*32

    float acc[2][8][4];
#pragma unroll
    for (int mt = 0; mt < 2; mt++)
#pragma unroll
        for (int j = 0; j < 8; j++)
#pragma unroll
            for (int q = 0; q < 4; q++) acc[mt][j][q] = 0.0f;

    float2 xb[2][2][4];    // [buf][mt][q]

#define LDX(t, dst) do {                                              \
        const size_t _o = (size_t)(t) * KT;                           \
        _Pragma("unroll")                                             \
        for (int _mt = 0; _mt < 2; _mt++) {                           \
            (dst)[_mt][0] = *(const float2*)(xp[_mt][0] + _o);        \
            (dst)[_mt][1] = *(const float2*)(xp[_mt][1] + _o);        \
            (dst)[_mt][2] = *(const float2*)(xp[_mt][0] + _o + 8);    \
            (dst)[_mt][3] = *(const float2*)(xp[_mt][1] + _o + 8);    \
        }                                                             \
    } while (0)

    LDX(par, xb[0]);

#pragma unroll 2
    for (int i = 0; i < NPW; i++) {
        const int cur = i & 1;
        const int t = 2 * i + par;
        if (i + 1 < NPW) LDX(t + 2, xb[cur ^ 1]);

        const uint4* bt = bp + (size_t)t * 512;
        uint4 bfa[4];
#pragma unroll
        for (int jj = 0; jj < 4; jj++) bfa[jj] = bt[jj * 32];

        uint32_t ahi[2][4], alo[2][4];
#pragma unroll
        for (int mt = 0; mt < 2; mt++)
#pragma unroll
            for (int q = 0; q < 4; q++) {
                float vx = xb[cur][mt][q].x, vy = xb[cur][mt][q].y;
                uint32_t ux = __float_as_uint(vx);
                uint32_t uy = __float_as_uint(vy);
                ahi[mt][q] = prmt_hi(ux, uy);
                alo[mt][q] = cvt_bf2(vx - __uint_as_float(ux & 0xFFFF0000u),
                                     vy - __uint_as_float(uy & 0xFFFF0000u));
            }

#pragma unroll
        for (int jj = 0; jj < 4; jj++)
#pragma unroll
            for (int mt = 0; mt < 2; mt++) {
                mma_bf16(acc[mt][jj], ahi[mt], bfa[jj].x, bfa[jj].y);
                mma_bf16(acc[mt][jj], ahi[mt], bfa[jj].z, bfa[jj].w);
                mma_bf16(acc[mt][jj], alo[mt], bfa[jj].x, bfa[jj].y);
            }

        uint4 bfb[4];
#pragma unroll
        for (int jj = 0; jj < 4; jj++) bfb[jj] = bt[(4 + jj) * 32];
#pragma unroll
        for (int jj = 0; jj < 4; jj++)
#pragma unroll
            for (int mt = 0; mt < 2; mt++) {
                mma_bf16(acc[mt][4 + jj], ahi[mt], bfb[jj].x, bfb[jj].y);
                mma_bf16(acc[mt][4 + jj], ahi[mt], bfb[jj].z, bfb[jj].w);
                mma_bf16(acc[mt][4 + jj], alo[mt], bfb[jj].x, bfb[jj].y);
            }
    }
#undef LDX
    __syncthreads();

    // 4-way partial reduction (par x kh) into smem logits [64][68], + bias
    const int grp = wid >> 1;            // par*2 + kh: phases 3..0
#pragma unroll
    for (int phase = 3; phase >= 0; phase--) {
        if (grp == phase) {
#pragma unroll
            for (int mt = 0; mt < 2; mt++)
#pragma unroll
                for (int j = 0; j < 8; j++) {
                    int row = rbw + mt * 16 + gid;
                    int col = j * 8 + 2 * tig;
                    if (phase == 3) {
                        slog[row * 68 + col]           = acc[mt][j][0];
                        slog[row * 68 + col + 1]       = acc[mt][j][1];
                        slog[(row + 8) * 68 + col]     = acc[mt][j][2];
                        slog[(row + 8) * 68 + col + 1] = acc[mt][j][3];
                    } else if (phase > 0) {
                        slog[row * 68 + col]           += acc[mt][j][0];
                        slog[row * 68 + col + 1]       += acc[mt][j][1];
                        slog[(row + 8) * 68 + col]     += acc[mt][j][2];
                        slog[(row + 8) * 68 + col + 1] += acc[mt][j][3];
                    } else {
                        slog[row * 68 + col]           += acc[mt][j][0] + sbias[col];
                        slog[row * 68 + col + 1]       += acc[mt][j][1] + sbias[col + 1];
                        slog[(row + 8) * 68 + col]     += acc[mt][j][2] + sbias[col];
                        slog[(row + 8) * 68 + col + 1] += acc[mt][j][3] + sbias[col + 1];
                    }
                }
        }
        __syncthreads();
    }

    // epilogue: one thread per row; top-4 + softmax; flag near-ties
    if (tid < BM) {
        const int r = tid;
        float d[64];
#pragma unroll
        for (int e4 = 0; e4 < 16; e4++) {
            float4 v = *(const float4*)(slog + r * 68 + e4 * 4);
            d[e4 * 4] = v.x; d[e4 * 4 + 1] = v.y; d[e4 * 4 + 2] = v.z; d[e4 * 4 + 3] = v.w;
        }
        float m1 = -1e30f, m2 = -1e30f, m3 = -1e30f, m4 = -1e30f;
        int i1 = 0, i2 = 0, i3 = 0, i4 = 0;
#pragma unroll
        for (int e = 0; e < 64; e++) {
            float v = d[e];
            if (v > m1)      { m4=m3;i4=i3; m3=m2;i3=i2; m2=m1;i2=i1; m1=v;i1=e; }
            else if (v > m2) { m4=m3;i4=i3; m3=m2;i3=i2; m2=v;i2=e; }
            else if (v > m3) { m4=m3;i4=i3; m3=v;i3=e; }
            else if (v > m4) { m4=v;i4=e; }
        }
        float s = 0.0f;
#pragma unroll
        for (int e = 0; e < 64; e++) s += __expf(d[e] - m1);
        float g1 = 1.0f / s;
        float g2 = __expf(m2 - m1) / s;

        float* orow = out_mask + (size_t)(row0 + r) * E_DIM;
#pragma unroll
        for (int e4 = 0; e4 < 16; e4++) {
            float4 v;
            int e = e4 * 4;
            v.x = (e     == i1) ? g1 : ((e     == i2) ? g2 : 0.0f);
            v.y = (e + 1 == i1) ? g1 : ((e + 1 == i2) ? g2 : 0.0f);
            v.z = (e + 2 == i1) ? g1 : ((e + 2 == i2) ? g2 : 0.0f);
            v.w = (e + 3 == i1) ? g1 : ((e + 3 == i2) ? g2 : 0.0f);
            *(float4*)(orow + e) = v;
        }
        if (write_idx) {
            float2 ix = make_float2((float)i1, (float)i2);
            *(float2*)(out_idx + (size_t)(row0 + r) * 2) = ix;
        }
        if ((m1 - m2 < TAU) || (m2 - m3 < TAU) || (m3 - m4 < TAU)) {
            int f = atomicAdd(&s_cnt, 1);
            if (f < MAXFLAG) {
                s_fr[f] = r;
                s_fc[f] = make_int4(i1, i2, i3, i4);
                s_fs[f] = s;
                s_fm[f] = m1;
            }
        }
    }
    __syncthreads();

    // rescue: one warp per flagged row; recompute 4 candidate logits exactly in fp32
    int cnt = min(s_cnt, MAXFLAG);
    for (int f = wid; f < cnt; f += 8) {
        const int r = s_fr[f];
        const int4 c = s_fc[f];
        const float sden = s_fs[f], m1a = s_fm[f];
        const float* xr = x + (size_t)(row0 + r) * D_DIM;
        float a0 = 0.f, a1 = 0.f, a2 = 0.f, a3 = 0.f;
        for (int k = lane; k < D_DIM; k += 32) {
            float xv = xr[k];
            a0 = fmaf(xv, g_wk[(size_t)c.x * D_DIM + k], a0);
            a1 = fmaf(xv, g_wk[(size_t)c.y * D_DIM + k], a1);
            a2 = fmaf(xv, g_wk[(size_t)c.z * D_DIM + k], a2);
            a3 = fmaf(xv, g_wk[(size_t)c.w * D_DIM + k], a3);
        }
#pragma unroll
        for (int off = 16; off; off >>= 1) {
            a0 += __shfl_xor_sync(0xffffffffu, a0, off);
            a1 += __shfl_xor_sync(0xffffffffu, a1, off);
            a2 += __shfl_xor_sync(0xffffffffu, a2, off);
            a3 += __shfl_xor_sync(0xffffffffu, a3, off);
        }
        float lv[4] = { a0 + sbias[c.x], a1 + sbias[c.y], a2 + sbias[c.z], a3 + sbias[c.w] };
        int   li[4] = { c.x, c.y, c.z, c.w };
#pragma unroll
        for (int p = 0; p < 3; p++)
#pragma unroll
            for (int q2 = 0; q2 < 3 - p; q2++) {
                bool sw = (lv[q2 + 1] > lv[q2]) ||
                          (lv[q2 + 1] == lv[q2] && li[q2 + 1] < li[q2]);
                if (sw) {
                    float tv = lv[q2]; lv[q2] = lv[q2 + 1]; lv[q2 + 1] = tv;
                    int  ti2 = li[q2]; li[q2] = li[q2 + 1]; li[q2 + 1] = ti2;
                }
            }
        float ng1 = __expf(lv[0] - m1a) / sden;
        float ng2 = __expf(lv[1] - m1a) / sden;
        int j1 = li[0], j2 = li[1];

        float* orow = out_mask + (size_t)(row0 + r) * E_DIM;
#pragma unroll
        for (int p = 0; p < 2; p++) {
            int e = lane + p * 32;
            orow[e] = (e == j1) ? ng1 : ((e == j2) ? ng2 : 0.0f);
        }
        if (write_idx && lane == 0) {
            float2 ix = make_float2((float)j1, (float)j2);
            *(float2*)(out_idx + (size_t)(row0 + r) * 2) = ix;
        }
    }
}

extern "C" void kernel_launch(void* const* d_in, const int* in_sizes, int n_in,
                              void* d_out, int out_size) {
    const float* x = (const float*)d_in[0];
    const float* W = (const float*)d_in[1];
    const float* b = (const float*)d_in[2];
    float* out     = (float*)d_out;
    float* out_idx = out + (size_t)N_ROWS * E_DIM;
    int write_idx  = (out_size >= N_ROWS * (E_DIM + 2)) ? 1 : 0;

    wpack_kernel<<<256, 256>>>(W);
    router_main<<<N_ROWS / BM, THREADS>>>(x, b, out, out_idx, write_idx);
}

// round 13
// speedup vs baseline: 1.7342x; 1.0613x over previous
#include <cuda_runtime.h>
#include <math.h>
#include <stdint.h>

#define N_ROWS 16384
#define D_DIM  2048
#define E_DIM  64
#define BM     64
#define KT     32
#define NT     (D_DIM / KT)        // 64 tiles, each warp does all of them (its k16 half)
#define THREADS 256
#define TAU 5e-4f
#define MAXFLAG 64

__device__ __forceinline__ uint32_t prmt_hi(uint32_t a, uint32_t b) {
    uint32_t d; asm("prmt.b32 %0, %1, %2, 0x7632;" : "=r"(d) : "r"(a), "r"(b)); return d;
}
__device__ __forceinline__ uint32_t cvt_bf2(float lo, float hi) {
    uint32_t d; asm("cvt.rn.bf16x2.f32 %0, %1, %2;" : "=r"(d) : "f"(hi), "f"(lo)); return d;
}
__device__ __forceinline__ void mma_bf16(float* c, const uint32_t* a,
                                         uint32_t b0, uint32_t b1) {
    asm volatile(
        "mma.sync.aligned.m16n8k16.row.col.f32.bf16.bf16.f32 "
        "{%0,%1,%2,%3}, {%4,%5,%6,%7}, {%8,%9}, {%0,%1,%2,%3};"
        : "+f"(c[0]), "+f"(c[1]), "+f"(c[2]), "+f"(c[3])
        : "r"(a[0]), "r"(a[1]), "r"(a[2]), "r"(a[3]), "r"(b0), "r"(b1));
}

// B fragment-ready: linear index c*256 + j*32 + lane (c = k16-chunk), uint4
// = {b0_hi, b1_hi, b0_lo, b1_lo}
__device__ uint4 g_wb[128 * 8 * 32];
// exact W, K-major: g_wk[e][k]
__device__ float g_wk[E_DIM * D_DIM];

__global__ void wpack_kernel(const float* __restrict__ W) {
    int idx = blockIdx.x * blockDim.x + threadIdx.x;   // 65536
    if (idx < 32768) {
        int lane = idx & 31, j = (idx >> 5) & 7, c = idx >> 8;
        int tig = lane & 3, gid = lane >> 2;
        int n = j * 8 + gid, k0 = c * 16;
        float w0 = W[(size_t)(k0 + 2 * tig)     * E_DIM + n];
        float w1 = W[(size_t)(k0 + 2 * tig + 1) * E_DIM + n];
        float w2 = W[(size_t)(k0 + 2 * tig + 8) * E_DIM + n];
        float w3 = W[(size_t)(k0 + 2 * tig + 9) * E_DIM + n];
        uint32_t u0 = __float_as_uint(w0), u1 = __float_as_uint(w1);
        uint32_t u2 = __float_as_uint(w2), u3 = __float_as_uint(w3);
        uint4 v;
        v.x = prmt_hi(u0, u1);
        v.y = prmt_hi(u2, u3);
        v.z = cvt_bf2(w0 - __uint_as_float(u0 & 0xFFFF0000u),
                      w1 - __uint_as_float(u1 & 0xFFFF0000u));
        v.w = cvt_bf2(w2 - __uint_as_float(u2 & 0xFFFF0000u),
                      w3 - __uint_as_float(u3 & 0xFFFF0000u));
        g_wb[idx] = v;
    }
    {   // exact copy, coalesced writes
        int e  = idx >> 10;
        int k2 = (idx & 1023) * 2;
        g_wk[(size_t)e * D_DIM + k2]     = W[(size_t)k2 * E_DIM + e];
        g_wk[(size_t)e * D_DIM + k2 + 1] = W[(size_t)(k2 + 1) * E_DIM + e];
    }
}

__global__ __launch_bounds__(THREADS, 2)
void router_main(const float* __restrict__ x,
                 const float* __restrict__ bias,
                 float* __restrict__ out_mask,
                 float* __restrict__ out_idx,
                 int write_idx)
{
    __shared__ float slog[BM * 68];
    __shared__ float sbias[E_DIM];
    __shared__ int   s_cnt;
    __shared__ int   s_fr[MAXFLAG];
    __shared__ int4  s_fc[MAXFLAG];
    __shared__ float s_fs[MAXFLAG];
    __shared__ float s_fm[MAXFLAG];

    const int tid  = threadIdx.x;
    const int wid  = tid >> 5;
    const int lane = tid & 31;
    const int gid  = lane >> 2;
    const int tig  = lane & 3;
    const int rbw  = (wid & 1) * 32;    // warp row block (M=32)
    const int nh   = (wid >> 1) & 1;    // N half (32 experts)
    const int kh   = (wid >> 2) & 1;    // k16 chunk within tile
    const int row0 = blockIdx.x * BM;

    if (tid < E_DIM) sbias[tid] = bias[tid];
    if (tid == 0) s_cnt = 0;

    // per-thread x row pointers [mt][h], col offset kh*16 + 2*tig baked in
    const float* xp[2][2];
#pragma unroll
    for (int mt = 0; mt < 2; mt++)
#pragma unroll
        for (int h = 0; h < 2; h++)
            xp[mt][h] = x + (size_t)(row0 + rbw + mt * 16 + 8 * h + gid) * D_DIM
                          + kh * 16 + 2 * tig;

    const uint4* bp = g_wb + (nh * 4) * 32 + lane;   // + c*256 + jj*32

    float acc[2][4][4];
#pragma unroll
    for (int mt = 0; mt < 2; mt++)
#pragma unroll
        for (int j = 0; j < 4; j++)
#pragma unroll
            for (int q = 0; q < 4; q++) acc[mt][j][q] = 0.0f;

    float2 xb[2][2][4];    // [buf][mt][q]

#define LDX(t, dst) do {                                              \
        const size_t _o = (size_t)(t) * KT;                          \
        _Pragma("unroll")                                             \
        for (int _mt = 0; _mt < 2; _mt++) {                           \
            (dst)[_mt][0] = *(const float2*)(xp[_mt][0] + _o);        \
            (dst)[_mt][1] = *(const float2*)(xp[_mt][1] + _o);        \
            (dst)[_mt][2] = *(const float2*)(xp[_mt][0] + _o + 8);    \
            (dst)[_mt][3] = *(const float2*)(xp[_mt][1] + _o + 8);    \
        }                                                             \
    } while (0)

    LDX(0, xb[0]);
    LDX(1, xb[1]);

#pragma unroll 2
    for (int t = 0; t < NT; t++) {
        const int cur = t & 1;
        const int c = 2 * t + kh;

        // B fragments for this chunk (L2/L1 resident)
        const uint4* bt = bp + (size_t)c * 256;
        uint4 bf[4];
#pragma unroll
        for (int jj = 0; jj < 4; jj++) bf[jj] = bt[jj * 32];

        // convert x buffer (landed: issued 2 iterations ago)
        uint32_t ahi[2][4], alo[2][4];
#pragma unroll
        for (int mt = 0; mt < 2; mt++)
#pragma unroll
            for (int q = 0; q < 4; q++) {
                float vx = xb[cur][mt][q].x, vy = xb[cur][mt][q].y;
                uint32_t ux = __float_as_uint(vx);
                uint32_t uy = __float_as_uint(vy);
                ahi[mt][q] = prmt_hi(ux, uy);
                alo[mt][q] = cvt_bf2(vx - __uint_as_float(ux & 0xFFFF0000u),
                                     vy - __uint_as_float(uy & 0xFFFF0000u));
            }

        // refill the just-freed buffer: distance-2 prefetch
        if (t + 2 < NT) LDX(t + 2, xb[cur]);

#pragma unroll
        for (int jj = 0; jj < 4; jj++)
#pragma unroll
            for (int mt = 0; mt < 2; mt++) {
                mma_bf16(acc[mt][jj], ahi[mt], bf[jj].x, bf[jj].y);
                mma_bf16(acc[mt][jj], ahi[mt], bf[jj].z, bf[jj].w);
                mma_bf16(acc[mt][jj], alo[mt], bf[jj].x, bf[jj].y);
            }
    }
#undef LDX
    __syncthreads();

    // kh reduction into smem logits [64][68] (nh/rbw are disjoint), + bias
    if (kh == 1) {
#pragma unroll
        for (int mt = 0; mt < 2; mt++)
#pragma unroll
            for (int jj = 0; jj < 4; jj++) {
                int row = rbw + mt * 16 + gid;
                int col = nh * 32 + jj * 8 + 2 * tig;
                slog[row * 68 + col]           = acc[mt][jj][0];
                slog[row * 68 + col + 1]       = acc[mt][jj][1];
                slog[(row + 8) * 68 + col]     = acc[mt][jj][2];
                slog[(row + 8) * 68 + col + 1] = acc[mt][jj][3];
            }
    }
    __syncthreads();
    if (kh == 0) {
#pragma unroll
        for (int mt = 0; mt < 2; mt++)
#pragma unroll
            for (int jj = 0; jj < 4; jj++) {
                int row = rbw + mt * 16 + gid;
                int col = nh * 32 + jj * 8 + 2 * tig;
                slog[row * 68 + col]           += acc[mt][jj][0] + sbias[col];
                slog[row * 68 + col + 1]       += acc[mt][jj][1] + sbias[col + 1];
                slog[(row + 8) * 68 + col]     += acc[mt][jj][2] + sbias[col];
                slog[(row + 8) * 68 + col + 1] += acc[mt][jj][3] + sbias[col + 1];
            }
    }
    __syncthreads();

    // epilogue: one thread per row; top-4 + softmax; flag near-ties
    if (tid < BM) {
        const int r = tid;
        float d[64];
#pragma unroll
        for (int e4 = 0; e4 < 16; e4++) {
            float4 v = *(const float4*)(slog + r * 68 + e4 * 4);
            d[e4 * 4] = v.x; d[e4 * 4 + 1] = v.y; d[e4 * 4 + 2] = v.z; d[e4 * 4 + 3] = v.w;
        }
        float m1 = -1e30f, m2 = -1e30f, m3 = -1e30f, m4 = -1e30f;
        int i1 = 0, i2 = 0, i3 = 0, i4 = 0;
#pragma unroll
        for (int e = 0; e < 64; e++) {
            float v = d[e];
            if (v > m1)      { m4=m3;i4=i3; m3=m2;i3=i2; m2=m1;i2=i1; m1=v;i1=e; }
            else if (v > m2) { m4=m3;i4=i3; m3=m2;i3=i2; m2=v;i2=e; }
            else if (v > m3) { m4=m3;i4=i3; m3=v;i3=e; }
            else if (v > m4) { m4=v;i4=e; }
        }
        float s = 0.0f;
#pragma unroll
        for (int e = 0; e < 64; e++) s += __expf(d[e] - m1);
        float g1 = 1.0f / s;
        float g2 = __expf(m2 - m1) / s;

        float* orow = out_mask + (size_t)(row0 + r) * E_DIM;
#pragma unroll
        for (int e4 = 0; e4 < 16; e4++) {
            float4 v;
            int e = e4 * 4;
            v.x = (e     == i1) ? g1 : ((e     == i2) ? g2 : 0.0f);
            v.y = (e + 1 == i1) ? g1 : ((e + 1 == i2) ? g2 : 0.0f);
            v.z = (e + 2 == i1) ? g1 : ((e + 2 == i2) ? g2 : 0.0f);
            v.w = (e + 3 == i1) ? g1 : ((e + 3 == i2) ? g2 : 0.0f);
            *(float4*)(orow + e) = v;
        }
        if (write_idx) {
            float2 ix = make_float2((float)i1, (float)i2);
            *(float2*)(out_idx + (size_t)(row0 + r) * 2) = ix;
        }
        if ((m1 - m2 < TAU) || (m2 - m3 < TAU) || (m3 - m4 < TAU)) {
            int f = atomicAdd(&s_cnt, 1);
            if (f < MAXFLAG) {
                s_fr[f] = r;
                s_fc[f] = make_int4(i1, i2, i3, i4);
                s_fs[f] = s;
                s_fm[f] = m1;
            }
        }
    }
    __syncthreads();

    // rescue: one warp per flagged row; recompute 4 candidate logits exactly in fp32
    int cnt = min(s_cnt, MAXFLAG);
    for (int f = wid; f < cnt; f += 8) {
        const int r = s_fr[f];
        const int4 c = s_fc[f];
        const float sden = s_fs[f], m1a = s_fm[f];
        const float* xr = x + (size_t)(row0 + r) * D_DIM;
        float a0 = 0.f, a1 = 0.f, a2 = 0.f, a3 = 0.f;
        for (int k = lane; k < D_DIM; k += 32) {
            float xv = xr[k];
            a0 = fmaf(xv, g_wk[(size_t)c.x * D_DIM + k], a0);
            a1 = fmaf(xv, g_wk[(size_t)c.y * D_DIM + k], a1);
            a2 = fmaf(xv, g_wk[(size_t)c.z * D_DIM + k], a2);
            a3 = fmaf(xv, g_wk[(size_t)c.w * D_DIM + k], a3);
        }
#pragma unroll
        for (int off = 16; off; off >>= 1) {
            a0 += __shfl_xor_sync(0xffffffffu, a0, off);
            a1 += __shfl_xor_sync(0xffffffffu, a1, off);
            a2 += __shfl_xor_sync(0xffffffffu, a2, off);
            a3 += __shfl_xor_sync(0xffffffffu, a3, off);
        }
        float lv[4] = { a0 + sbias[c.x], a1 + sbias[c.y], a2 + sbias[c.z], a3 + sbias[c.w] };
        int   li[4] = { c.x, c.y, c.z, c.w };
#pragma unroll
        for (int p = 0; p < 3; p++)
#pragma unroll
            for (int q2 = 0; q2 < 3 - p; q2++) {
                bool sw = (lv[q2 + 1] > lv[q2]) ||
                          (lv[q2 + 1] == lv[q2] && li[q2 + 1] < li[q2]);
                if (sw) {
                    float tv = lv[q2]; lv[q2] = lv[q2 + 1]; lv[q2 + 1] = tv;
                    int  ti2 = li[q2]; li[q2] = li[q2 + 1]; li[q2 + 1] = ti2;
                }
            }
        float ng1 = __expf(lv[0] - m1a) / sden;
        float ng2 = __expf(lv[1] - m1a) / sden;
        int j1 = li[0], j2 = li[1];

        float* orow = out_mask + (size_t)(row0 + r) * E_DIM;
#pragma unroll
        for (int p = 0; p < 2; p++) {
            int e = lane + p * 32;
            orow[e] = (e == j1) ? ng1 : ((e == j2) ? ng2 : 0.0f);
        }
        if (write_idx && lane == 0) {
            float2 ix = make_float2((float)j1, (float)j2);
            *(float2*)(out_idx + (size_t)(row0 + r) * 2) = ix;
        }
    }
}

extern "C" void kernel_launch(void* const* d_in, const int* in_sizes, int n_in,
                              void* d_out, int out_size) {
    const float* x = (const float*)d_in[0];
    const float* W = (const float*)d_in[1];
    const float* b = (const float*)d_in[2];
    float* out     = (float*)d_out;
    float* out_idx = out + (size_t)N_ROWS * E_DIM;
    int write_idx  = (out_size >= N_ROWS * (E_DIM + 2)) ? 1 : 0;

    wpack_kernel<<<256, 256>>>(W);
    router_main<<<N_ROWS / BM, THREADS>>>(x, b, out, out_idx, write_idx);
}

// round 15
// speedup vs baseline: 1.7689x; 1.0200x over previous
#include <cuda_runtime.h>
#include <math.h>
#include <stdint.h>

#define N_ROWS 16384
#define D_DIM  2048
#define E_DIM  64
#define BM     64
#define KT     32
#define NT     (D_DIM / KT)        // 64 tiles, each warp does all of them (its k16 half)
#define THREADS 256
#define TAU 5e-4f
#define MAXFLAG 64

__device__ __forceinline__ uint32_t prmt_hi(uint32_t a, uint32_t b) {
    uint32_t d; asm("prmt.b32 %0, %1, %2, 0x7632;" : "=r"(d) : "r"(a), "r"(b)); return d;
}
__device__ __forceinline__ uint32_t cvt_bf2(float lo, float hi) {
    uint32_t d; asm("cvt.rn.bf16x2.f32 %0, %1, %2;" : "=r"(d) : "f"(hi), "f"(lo)); return d;
}
__device__ __forceinline__ void mma_bf16(float* c, const uint32_t* a,
                                         uint32_t b0, uint32_t b1) {
    asm volatile(
        "mma.sync.aligned.m16n8k16.row.col.f32.bf16.bf16.f32 "
        "{%0,%1,%2,%3}, {%4,%5,%6,%7}, {%8,%9}, {%0,%1,%2,%3};"
        : "+f"(c[0]), "+f"(c[1]), "+f"(c[2]), "+f"(c[3])
        : "r"(a[0]), "r"(a[1]), "r"(a[2]), "r"(a[3]), "r"(b0), "r"(b1));
}

// B fragment-ready: linear index c*256 + j*32 + lane (c = k16-chunk), uint4
// = {b0_hi, b1_hi, b0_lo, b1_lo}
__device__ uint4 g_wb[128 * 8 * 32];
// exact W, K-major: g_wk[e][k]
__device__ float g_wk[E_DIM * D_DIM];

__global__ void wpack_kernel(const float* __restrict__ W) {
    int idx = blockIdx.x * blockDim.x + threadIdx.x;   // 65536
    if (idx < 32768) {
        int lane = idx & 31, j = (idx >> 5) & 7, c = idx >> 8;
        int tig = lane & 3, gid = lane >> 2;
        int n = j * 8 + gid, k0 = c * 16;
        float w0 = W[(size_t)(k0 + 2 * tig)     * E_DIM + n];
        float w1 = W[(size_t)(k0 + 2 * tig + 1) * E_DIM + n];
        float w2 = W[(size_t)(k0 + 2 * tig + 8) * E_DIM + n];
        float w3 = W[(size_t)(k0 + 2 * tig + 9) * E_DIM + n];
        uint32_t u0 = __float_as_uint(w0), u1 = __float_as_uint(w1);
        uint32_t u2 = __float_as_uint(w2), u3 = __float_as_uint(w3);
        uint4 v;
        v.x = prmt_hi(u0, u1);
        v.y = prmt_hi(u2, u3);
        v.z = cvt_bf2(w0 - __uint_as_float(u0 & 0xFFFF0000u),
                      w1 - __uint_as_float(u1 & 0xFFFF0000u));
        v.w = cvt_bf2(w2 - __uint_as_float(u2 & 0xFFFF0000u),
                      w3 - __uint_as_float(u3 & 0xFFFF0000u));
        g_wb[idx] = v;
    }
    {   // exact copy, coalesced writes
        int e  = idx >> 10;
        int k2 = (idx & 1023) * 2;
        g_wk[(size_t)e * D_DIM + k2]     = W[(size_t)k2 * E_DIM + e];
        g_wk[(size_t)e * D_DIM + k2 + 1] = W[(size_t)(k2 + 1) * E_DIM + e];
    }
}

__global__ __launch_bounds__(THREADS, 2)
void router_main(const float* __restrict__ x,
                 const float* __restrict__ bias,
                 float* __restrict__ out_mask,
                 float* __restrict__ out_idx,
                 int write_idx)
{
    __shared__ float slog[BM * 68];
    __shared__ float sbias[E_DIM];
    __shared__ int   s_cnt;
    __shared__ int   s_fr[MAXFLAG];
    __shared__ int4  s_fc[MAXFLAG];
    __shared__ float s_fs[MAXFLAG];
    __shared__ float s_fm[MAXFLAG];

    const int tid  = threadIdx.x;
    const int wid  = tid >> 5;
    const int lane = tid & 31;
    const int gid  = lane >> 2;
    const int tig  = lane & 3;
    const int rbw  = (wid & 1) * 32;    // warp row block (M=32)
    const int nh   = (wid >> 1) & 1;    // N half (32 experts)
    const int kh   = (wid >> 2) & 1;    // k16 chunk within tile
    const int row0 = blockIdx.x * BM;

    if (tid < E_DIM) sbias[tid] = bias[tid];
    if (tid == 0) s_cnt = 0;

    // per-thread x row pointers [mt][h], col offset kh*16 + 2*tig baked in
    const float* xp[2][2];
#pragma unroll
    for (int mt = 0; mt < 2; mt++)
#pragma unroll
        for (int h = 0; h < 2; h++)
            xp[mt][h] = x + (size_t)(row0 + rbw + mt * 16 + 8 * h + gid) * D_DIM
                          + kh * 16 + 2 * tig;

    const uint4* bp = g_wb + (nh * 4) * 32 + lane;   // + c*256 + jj*32

    float acc[2][4][4];
#pragma unroll
    for (int mt = 0; mt < 2; mt++)
#pragma unroll
        for (int j = 0; j < 4; j++)
#pragma unroll
            for (int q = 0; q < 4; q++) acc[mt][j][q] = 0.0f;

    float2 xb[2][2][4];    // [buf][mt][q]

#define LDX(t, dst) do {                                              \
        const size_t _o = (size_t)(t) * KT;                          \
        _Pragma("unroll")                                             \
        for (int _mt = 0; _mt < 2; _mt++) {                           \
            (dst)[_mt][0] = *(const float2*)(xp[_mt][0] + _o);        \
            (dst)[_mt][1] = *(const float2*)(xp[_mt][1] + _o);        \
            (dst)[_mt][2] = *(const float2*)(xp[_mt][0] + _o + 8);    \
            (dst)[_mt][3] = *(const float2*)(xp[_mt][1] + _o + 8);    \
        }                                                             \
    } while (0)

    LDX(0, xb[0]);
    LDX(1, xb[1]);

#pragma unroll 2
    for (int t = 0; t < NT; t++) {
        const int cur = t & 1;
        const int c = 2 * t + kh;

        // B fragments for this chunk (L2/L1 resident)
        const uint4* bt = bp + (size_t)c * 256;
        uint4 bf[4];
#pragma unroll
        for (int jj = 0; jj < 4; jj++) bf[jj] = bt[jj * 32];

        // convert x buffer (landed: issued 2 iterations ago)
        uint32_t ahi[2][4], alo[2][4];
#pragma unroll
        for (int mt = 0; mt < 2; mt++)
#pragma unroll
            for (int q = 0; q < 4; q++) {
                float vx = xb[cur][mt][q].x, vy = xb[cur][mt][q].y;
                uint32_t ux = __float_as_uint(vx);
                uint32_t uy = __float_as_uint(vy);
                ahi[mt][q] = prmt_hi(ux, uy);
                alo[mt][q] = cvt_bf2(vx - __uint_as_float(ux & 0xFFFF0000u),
                                     vy - __uint_as_float(uy & 0xFFFF0000u));
            }

        // refill the just-freed buffer: distance-2 prefetch
        if (t + 2 < NT) LDX(t + 2, xb[cur]);

        // PASS-MAJOR MMA ORDER: all 8 independent (jj,mt) per split term, so
        // dependent accumulator reuses are 8 issues apart (RAW latency hidden).
#pragma unroll
        for (int jj = 0; jj < 4; jj++)
#pragma unroll
            for (int mt = 0; mt < 2; mt++)
                mma_bf16(acc[mt][jj], ahi[mt], bf[jj].x, bf[jj].y);
#pragma unroll
        for (int jj = 0; jj < 4; jj++)
#pragma unroll
            for (int mt = 0; mt < 2; mt++)
                mma_bf16(acc[mt][jj], ahi[mt], bf[jj].z, bf[jj].w);
#pragma unroll
        for (int jj = 0; jj < 4; jj++)
#pragma unroll
            for (int mt = 0; mt < 2; mt++)
                mma_bf16(acc[mt][jj], alo[mt], bf[jj].x, bf[jj].y);
    }
#undef LDX
    __syncthreads();

    // kh reduction into smem logits [64][68] (nh/rbw are disjoint), + bias
    if (kh == 1) {
#pragma unroll
        for (int mt = 0; mt < 2; mt++)
#pragma unroll
            for (int jj = 0; jj < 4; jj++) {
                int row = rbw + mt * 16 + gid;
                int col = nh * 32 + jj * 8 + 2 * tig;
                slog[row * 68 + col]           = acc[mt][jj][0];
                slog[row * 68 + col + 1]       = acc[mt][jj][1];
                slog[(row + 8) * 68 + col]     = acc[mt][jj][2];
                slog[(row + 8) * 68 + col + 1] = acc[mt][jj][3];
            }
    }
    __syncthreads();
    if (kh == 0) {
#pragma unroll
        for (int mt = 0; mt < 2; mt++)
#pragma unroll
            for (int jj = 0; jj < 4; jj++) {
                int row = rbw + mt * 16 + gid;
                int col = nh * 32 + jj * 8 + 2 * tig;
                slog[row * 68 + col]           += acc[mt][jj][0] + sbias[col];
                slog[row * 68 + col + 1]       += acc[mt][jj][1] + sbias[col + 1];
                slog[(row + 8) * 68 + col]     += acc[mt][jj][2] + sbias[col];
                slog[(row + 8) * 68 + col + 1] += acc[mt][jj][3] + sbias[col + 1];
            }
    }
    __syncthreads();

    // epilogue: one thread per row; top-4 + softmax; flag near-ties
    if (tid < BM) {
        const int r = tid;
        float d[64];
#pragma unroll
        for (int e4 = 0; e4 < 16; e4++) {
            float4 v = *(const float4*)(slog + r * 68 + e4 * 4);
            d[e4 * 4] = v.x; d[e4 * 4 + 1] = v.y; d[e4 * 4 + 2] = v.z; d[e4 * 4 + 3] = v.w;
        }
        float m1 = -1e30f, m2 = -1e30f, m3 = -1e30f, m4 = -1e30f;
        int i1 = 0, i2 = 0, i3 = 0, i4 = 0;
#pragma unroll
        for (int e = 0; e < 64; e++) {
            float v = d[e];
            if (v > m1)      { m4=m3;i4=i3; m3=m2;i3=i2; m2=m1;i2=i1; m1=v;i1=e; }
            else if (v > m2) { m4=m3;i4=i3; m3=m2;i3=i2; m2=v;i2=e; }
            else if (v > m3) { m4=m3;i4=i3; m3=v;i3=e; }
            else if (v > m4) { m4=v;i4=e; }
        }
        float s = 0.0f;
#pragma unroll
        for (int e = 0; e < 64; e++) s += __expf(d[e] - m1);
        float g1 = 1.0f / s;
        float g2 = __expf(m2 - m1) / s;

        float* orow = out_mask + (size_t)(row0 + r) * E_DIM;
#pragma unroll
        for (int e4 = 0; e4 < 16; e4++) {
            float4 v;
            int e = e4 * 4;
            v.x = (e     == i1) ? g1 : ((e     == i2) ? g2 : 0.0f);
            v.y = (e + 1 == i1) ? g1 : ((e + 1 == i2) ? g2 : 0.0f);
            v.z = (e + 2 == i1) ? g1 : ((e + 2 == i2) ? g2 : 0.0f);
            v.w = (e + 3 == i1) ? g1 : ((e + 3 == i2) ? g2 : 0.0f);
            *(float4*)(orow + e) = v;
        }
        if (write_idx) {
            float2 ix = make_float2((float)i1, (float)i2);
            *(float2*)(out_idx + (size_t)(row0 + r) * 2) = ix;
        }
        if ((m1 - m2 < TAU) || (m2 - m3 < TAU) || (m3 - m4 < TAU)) {
            int f = atomicAdd(&s_cnt, 1);
            if (f < MAXFLAG) {
                s_fr[f] = r;
                s_fc[f] = make_int4(i1, i2, i3, i4);
                s_fs[f] = s;
                s_fm[f] = m1;
            }
        }
    }
    __syncthreads();

    // rescue: one warp per flagged row; recompute 4 candidate logits exactly in fp32
    int cnt = min(s_cnt, MAXFLAG);
    for (int f = wid; f < cnt; f += 8) {
        const int r = s_fr[f];
        const int4 c = s_fc[f];
        const float sden = s_fs[f], m1a = s_fm[f];
        const float* xr = x + (size_t)(row0 + r) * D_DIM;
        float a0 = 0.f, a1 = 0.f, a2 = 0.f, a3 = 0.f;
        for (int k = lane; k < D_DIM; k += 32) {
            float xv = xr[k];
            a0 = fmaf(xv, g_wk[(size_t)c.x * D_DIM + k], a0);
            a1 = fmaf(xv, g_wk[(size_t)c.y * D_DIM + k], a1);
            a2 = fmaf(xv, g_wk[(size_t)c.z * D_DIM + k], a2);
            a3 = fmaf(xv, g_wk[(size_t)c.w * D_DIM + k], a3);
        }
#pragma unroll
        for (int off = 16; off; off >>= 1) {
            a0 += __shfl_xor_sync(0xffffffffu, a0, off);
            a1 += __shfl_xor_sync(0xffffffffu, a1, off);
            a2 += __shfl_xor_sync(0xffffffffu, a2, off);
            a3 += __shfl_xor_sync(0xffffffffu, a3, off);
        }
        float lv[4] = { a0 + sbias[c.x], a1 + sbias[c.y], a2 + sbias[c.z], a3 + sbias[c.w] };
        int   li[4] = { c.x, c.y, c.z, c.w };
#pragma unroll
        for (int p = 0; p < 3; p++)
#pragma unroll
            for (int q2 = 0; q2 < 3 - p; q2++) {
                bool sw = (lv[q2 + 1] > lv[q2]) ||
                          (lv[q2 + 1] == lv[q2] && li[q2 + 1] < li[q2]);
                if (sw) {
                    float tv = lv[q2]; lv[q2] = lv[q2 + 1]; lv[q2 + 1] = tv;
                    int  ti2 = li[q2]; li[q2] = li[q2 + 1]; li[q2 + 1] = ti2;
                }
            }
        float ng1 = __expf(lv[0] - m1a) / sden;
        float ng2 = __expf(lv[1] - m1a) / sden;
        int j1 = li[0], j2 = li[1];

        float* orow = out_mask + (size_t)(row0 + r) * E_DIM;
#pragma unroll
        for (int p = 0; p < 2; p++) {
            int e = lane + p * 32;
            orow[e] = (e == j1) ? ng1 : ((e == j2) ? ng2 : 0.0f);
        }
        if (write_idx && lane == 0) {
            float2 ix = make_float2((float)j1, (float)j2);
            *(float2*)(out_idx + (size_t)(row0 + r) * 2) = ix;
        }
    }
}

extern "C" void kernel_launch(void* const* d_in, const int* in_sizes, int n_in,
                              void* d_out, int out_size) {
    const float* x = (const float*)d_in[0];
    const float* W = (const float*)d_in[1];
    const float* b = (const float*)d_in[2];
    float* out     = (float*)d_out;
    float* out_idx = out + (size_t)N_ROWS * E_DIM;
    int write_idx  = (out_size >= N_ROWS * (E_DIM + 2)) ? 1 : 0;

    wpack_kernel<<<256, 256>>>(W);
    router_main<<<N_ROWS / BM, THREADS>>>(x, b, out, out_idx, write_idx);
}